// round 2
// baseline (speedup 1.0000x reference)
#include <cuda_runtime.h>
#include <math.h>
#include <stdint.h>

// ---------------------------------------------------------------------------
// Two-layer tanh RNN.  SEQ=512, BATCH=64, IN=HD=1024, fp32.
//   h1(t) = tanh(x(t)@Wi0^T + bi0 + h1(t-1)@Wh0^T + bh0)
//   h2(t) = tanh(h1(t)@Wi1^T + bi1 + h2(t-1)@Wh1^T + bh1)
// Output: outputs[512,64,1024] (h2 per step) ++ h_final[2,64,1024].
//
// Structure:
//   1) reset kernel      : zero grid-barrier counter + initial hidden state
//   2) precompute kernel : P = x@Wi0^T + bi0 + bh0  (big parallel fp32 GEMM)
//   3) persistent kernel : 512 steps, 128 CTAs (one wave), weights in SMEM,
//                          hardened grid sync between phases.
// ---------------------------------------------------------------------------

#define SEQ   512
#define BATCH 64
#define HD    1024
#define MTOT  (SEQ*BATCH)                    // 32768
#define OUT_MAIN ((size_t)SEQ*BATCH*HD)      // 33554432

#define NCTA 128
#define TPB  256
#define NSL  8                               // output columns per CTA

// dynamic smem layout (in floats)
#define STG_ROW   68                         // 64 + pad (bank-conflict avoidance)
#define STG_SZ    (64*STG_ROW)               // one stage buffer: 64 rows x 64 k
#define SW_FLOATS (3*NSL*HD)                 // 24576
#define STG_OFF   SW_FLOATS
#define SREDA_OFF (STG_OFF + 4*STG_SZ)       // 24576 + 17408 = 41984
#define SREDB_OFF (SREDA_OFF + 512)
#define SMEM_FLOATS (SREDB_OFF + 512)        // 43008
#define SMEM_BYTES  (SMEM_FLOATS*4)          // 172032 bytes

// scratch (device globals: no allocations allowed)
__device__ float g_P[33554432];              // 128 MB precomputed input term
__device__ float g_h1[2][BATCH*HD];
__device__ float g_h2[2][BATCH*HD];
__device__ unsigned g_count;

// ---------------------------------------------------------------------------
// 1) reset: zero the barrier counter and initial hidden states (per launch,
//    so graph replays are deterministic).
// ---------------------------------------------------------------------------
__global__ void rnn_reset_kernel() {
    unsigned idx = blockIdx.x * blockDim.x + threadIdx.x;
    if (idx == 0) g_count = 0u;
    if (idx < BATCH*HD) {
        g_h1[0][idx] = 0.f;
        g_h2[0][idx] = 0.f;
    }
}

// ---------------------------------------------------------------------------
// 2) precompute: P[m][n] = sum_k X[m][k]*Wi0[n][k] + bi0[n] + bh0[n]
//    Classic 64x64 tile, BK=16, 256 threads, 4x4 register tile.
// ---------------------------------------------------------------------------
__global__ __launch_bounds__(256)
void rnn_precompute_kernel(const float* __restrict__ X,
                           const float* __restrict__ Wi0,
                           const float* __restrict__ bi0,
                           const float* __restrict__ bh0)
{
    __shared__ float As[16][68];
    __shared__ float Bs[16][68];

    const int bm = blockIdx.y * 64;
    const int bn = blockIdx.x * 64;
    const int tid = threadIdx.x;
    const int ty = tid >> 4, tx = tid & 15;
    const int m0 = ty * 4, n0 = tx * 4;
    const int lm = tid >> 2;
    const int lk = (tid & 3) * 4;

    const float* Ap = X   + (size_t)(bm + lm) * HD + lk;
    const float* Bp = Wi0 + (size_t)(bn + lm) * HD + lk;

    float4 a = *(const float4*)Ap;
    float4 b = *(const float4*)Bp;

    float acc[4][4];
#pragma unroll
    for (int i = 0; i < 4; i++)
#pragma unroll
        for (int j = 0; j < 4; j++) acc[i][j] = 0.f;

    for (int k0 = 0; k0 < HD; k0 += 16) {
        __syncthreads();
        As[lk+0][lm] = a.x; As[lk+1][lm] = a.y; As[lk+2][lm] = a.z; As[lk+3][lm] = a.w;
        Bs[lk+0][lm] = b.x; Bs[lk+1][lm] = b.y; Bs[lk+2][lm] = b.z; Bs[lk+3][lm] = b.w;
        __syncthreads();
        if (k0 + 16 < HD) {
            a = *(const float4*)(Ap + k0 + 16);
            b = *(const float4*)(Bp + k0 + 16);
        }
#pragma unroll
        for (int k = 0; k < 16; k++) {
            const float4 av = *(const float4*)&As[k][m0];
            const float4 bv = *(const float4*)&Bs[k][n0];
            float am[4] = {av.x, av.y, av.z, av.w};
            float bb[4] = {bv.x, bv.y, bv.z, bv.w};
#pragma unroll
            for (int i = 0; i < 4; i++)
#pragma unroll
                for (int j = 0; j < 4; j++) acc[i][j] += am[i] * bb[j];
        }
    }

    const int gn = bn + n0;
    float b0[4];
#pragma unroll
    for (int j = 0; j < 4; j++) b0[j] = bi0[gn + j] + bh0[gn + j];
#pragma unroll
    for (int i = 0; i < 4; i++) {
        float4 r;
        r.x = acc[i][0] + b0[0];
        r.y = acc[i][1] + b0[1];
        r.z = acc[i][2] + b0[2];
        r.w = acc[i][3] + b0[3];
        *(float4*)&g_P[(size_t)(bm + m0 + i) * HD + gn] = r;
    }
}

// ---------------------------------------------------------------------------
// 3) persistent recurrent kernel
// ---------------------------------------------------------------------------
__device__ __forceinline__ void barx(int id) {
    asm volatile("bar.sync %0, %1;" :: "r"(id), "r"(128) : "memory");
}

// Canonical cooperative-style grid barrier:
//   every thread fences its own writes -> block barrier -> thread 0 arrives
//   (release via fence+atomic) and spins with backoff -> fence -> barrier.
__device__ __forceinline__ void grid_sync(unsigned& target) {
    __threadfence();                 // order THIS thread's h-state stores
    __syncthreads();
    target += NCTA;
    if (threadIdx.x == 0) {
        atomicAdd(&g_count, 1u);
        unsigned v;
        do {
            v = *((volatile unsigned*)&g_count);
            if (v >= target) break;
            __nanosleep(64);
        } while (true);
        __threadfence();             // acquire: make peers' stores visible
    }
    __syncthreads();
}

// One half (128 threads) accumulates acc[4] = sum over [kstart, kstart+klen)
// of hsrc[b][k] * W[n][k] for its 4 output columns. h is staged coalesced
// into double-buffered SMEM (named barrier per half), weights come from SMEM.
__device__ __forceinline__ void accum_half(
    float acc[4], const float* __restrict__ hsrc, const float* __restrict__ sW,
    int kstart, int klen, float* stg0, float* stg1,
    int barid, int ht, int b, int nq)
{
    acc[0] = acc[1] = acc[2] = acc[3] = 0.f;
    const int rbase = ht >> 4;          // 0..7
    const int kk    = (ht & 15) << 2;   // 0..60

    // prefetch chunk 0 into stg0
#pragma unroll
    for (int p = 0; p < 8; p++) {
        const int row = (p << 3) + rbase;
        float4 v = __ldcg(reinterpret_cast<const float4*>(
            hsrc + (size_t)row * HD + kstart + kk));
        *reinterpret_cast<float4*>(stg0 + row * STG_ROW + kk) = v;
    }

    const int nchunk = klen >> 6;
    for (int c = 0; c < nchunk; c++) {
        float* cur = (c & 1) ? stg1 : stg0;
        float* nxt = (c & 1) ? stg0 : stg1;
        barx(barid);                    // drains STS into cur; frees nxt
        if (c + 1 < nchunk) {
            const int kp = kstart + ((c + 1) << 6);
#pragma unroll
            for (int p = 0; p < 8; p++) {
                const int row = (p << 3) + rbase;
                float4 v = __ldcg(reinterpret_cast<const float4*>(
                    hsrc + (size_t)row * HD + kp + kk));
                *reinterpret_cast<float4*>(nxt + row * STG_ROW + kk) = v;
            }
        }
        const int kof = kstart + (c << 6);
        const float* hrow = cur + b * STG_ROW;
        const float* w0 = sW + (nq * 4 + 0) * HD + kof;
        const float* w1 = w0 + HD;
        const float* w2 = w1 + HD;
        const float* w3 = w2 + HD;
#pragma unroll
        for (int k4 = 0; k4 < 16; k4++) {
            const float4 hv = *(const float4*)(hrow + (k4 << 2));
            const float4 a0 = *(const float4*)(w0 + (k4 << 2));
            acc[0] += hv.x*a0.x + hv.y*a0.y + hv.z*a0.z + hv.w*a0.w;
            const float4 a1 = *(const float4*)(w1 + (k4 << 2));
            acc[1] += hv.x*a1.x + hv.y*a1.y + hv.z*a1.z + hv.w*a1.w;
            const float4 a2 = *(const float4*)(w2 + (k4 << 2));
            acc[2] += hv.x*a2.x + hv.y*a2.y + hv.z*a2.z + hv.w*a2.w;
            const float4 a3 = *(const float4*)(w3 + (k4 << 2));
            acc[3] += hv.x*a3.x + hv.y*a3.y + hv.z*a3.z + hv.w*a3.w;
        }
    }
}

__global__ __launch_bounds__(TPB)
void rnn_recurrent_kernel(const float* __restrict__ Wh0,
                          const float* __restrict__ Wi1,
                          const float* __restrict__ Wh1,
                          const float* __restrict__ bi1,
                          const float* __restrict__ bh1,
                          float* __restrict__ out,
                          int write_final)
{
    extern __shared__ float smem[];
    float* sWh0  = smem;
    float* sWi1  = smem + NSL*HD;
    float* sWh1  = smem + 2*NSL*HD;
    float* stg   = smem + STG_OFF;
    float* sredA = smem + SREDA_OFF;
    float* sredB = smem + SREDB_OFF;

    const int tid   = threadIdx.x;
    const int nbase = blockIdx.x * NSL;
    const int half  = tid >> 7;     // 0 or 1 (warps 0-3 / 4-7)
    const int ht    = tid & 127;
    const int b     = ht >> 1;      // batch row 0..63
    const int nq    = ht & 1;       // which 4-column quad
    const int barid = half + 1;     // named barriers 1 / 2
    float* stg0 = stg + (half * 2 + 0) * STG_SZ;
    float* stg1 = stg + (half * 2 + 1) * STG_SZ;

    // load the CTA's 8-column weight slices into SMEM (resident all 512 steps)
    {
        const float* w0 = Wh0 + (size_t)nbase * HD;
        const float* w1 = Wi1 + (size_t)nbase * HD;
        const float* w2 = Wh1 + (size_t)nbase * HD;
        for (int i = tid * 4; i < NSL * HD; i += TPB * 4) {
            *(float4*)(sWh0 + i) = *(const float4*)(w0 + i);
            *(float4*)(sWi1 + i) = *(const float4*)(w1 + i);
            *(float4*)(sWh1 + i) = *(const float4*)(w2 + i);
        }
    }

    // per-thread epilogue constants (2 outputs each)
    float bias2[2];
    int eb_[2], en_[2];
#pragma unroll
    for (int e = 0; e < 2; e++) {
        const int oo = tid * 2 + e;
        eb_[e] = oo >> 3;
        en_[e] = oo & 7;
        bias2[e] = bi1[nbase + en_[e]] + bh1[nbase + en_[e]];
    }
    __syncthreads();

    unsigned target = 0;
    for (int t = 0; t < SEQ; t++) {
        const int rb = t & 1, wb = rb ^ 1;
        const float* h1p = g_h1[rb];
        float*       h1n = g_h1[wb];
        const float* h2p = g_h2[rb];
        float*       h2n = g_h2[wb];
        const int last = (t == SEQ - 1);

        float acc[4];

        // ---------- Layer 1: h1 = tanh(P(t) + h1p @ Wh0^T) ----------
        // half 0: k in [0,512), half 1: k in [512,1024)
        accum_half(acc, h1p, sWh0, half * 512, 512, stg0, stg1, barid, ht, b, nq);
        {
            float* sr = half ? sredB : sredA;
            const int o = b * NSL + nq * 4;
            sr[o+0] = acc[0]; sr[o+1] = acc[1]; sr[o+2] = acc[2]; sr[o+3] = acc[3];
        }
        __syncthreads();
        {
            const float* Pt = g_P + (size_t)t * BATCH * HD;
#pragma unroll
            for (int e = 0; e < 2; e++) {
                const int oo = tid * 2 + e;
                float v = sredA[oo] + sredB[oo]
                        + Pt[(size_t)eb_[e] * HD + nbase + en_[e]];
                v = tanhf(v);
                __stcg(h1n + (size_t)eb_[e] * HD + nbase + en_[e], v);
                if (write_final && last)
                    out[OUT_MAIN + (size_t)eb_[e] * HD + nbase + en_[e]] = v;
            }
        }
        grid_sync(target);

        // ---------- Layer 2: h2 = tanh(h1 @ Wi1^T + h2p @ Wh1^T + b) ----------
        // half 0: Wi1 with fresh h1 (full K); half 1: Wh1 with h2p (full K)
        accum_half(acc, half ? h2p : h1n, half ? sWh1 : sWi1,
                   0, HD, stg0, stg1, barid, ht, b, nq);
        {
            float* sr = half ? sredB : sredA;
            const int o = b * NSL + nq * 4;
            sr[o+0] = acc[0]; sr[o+1] = acc[1]; sr[o+2] = acc[2]; sr[o+3] = acc[3];
        }
        __syncthreads();
        {
#pragma unroll
            for (int e = 0; e < 2; e++) {
                const int oo = tid * 2 + e;
                float v = sredA[oo] + sredB[oo] + bias2[e];
                v = tanhf(v);
                __stcg(h2n + (size_t)eb_[e] * HD + nbase + en_[e], v);
                out[(size_t)t * BATCH * HD + (size_t)eb_[e] * HD + nbase + en_[e]] = v;
                if (write_final && last)
                    out[OUT_MAIN + (size_t)BATCH * HD
                        + (size_t)eb_[e] * HD + nbase + en_[e]] = v;
            }
        }
        grid_sync(target);
    }
}

// ---------------------------------------------------------------------------
// launcher
// ---------------------------------------------------------------------------
extern "C" void kernel_launch(void* const* d_in, const int* in_sizes, int n_in,
                              void* d_out, int out_size) {
    const float* x   = (const float*)d_in[0];
    const float* Wi0 = (const float*)d_in[1];
    const float* bi0 = (const float*)d_in[2];
    const float* Wh0 = (const float*)d_in[3];
    const float* bh0 = (const float*)d_in[4];
    const float* Wi1 = (const float*)d_in[5];
    const float* bi1 = (const float*)d_in[6];
    const float* Wh1 = (const float*)d_in[7];
    const float* bh1 = (const float*)d_in[8];
    float* out = (float*)d_out;

    const int write_final =
        ((size_t)out_size >= OUT_MAIN + (size_t)2 * BATCH * HD) ? 1 : 0;

    // idempotent, host-side only; safe under graph capture
    cudaFuncSetAttribute(rnn_recurrent_kernel,
                         cudaFuncAttributeMaxDynamicSharedMemorySize, SMEM_BYTES);

    rnn_reset_kernel<<<(BATCH*HD + 255) / 256, 256>>>();
    rnn_precompute_kernel<<<dim3(HD/64, MTOT/64), 256>>>(x, Wi0, bi0, bh0);
    rnn_recurrent_kernel<<<NCTA, TPB, SMEM_BYTES>>>(Wh0, Wi1, Wh1, bi1, bh1,
                                                    out, write_final);
}